// round 12
// baseline (speedup 1.0000x reference)
#include <cuda_runtime.h>
#include <cstdint>

#define N_ROWS 32768
#define D      256
#define K      8192
#define BM     128
#define NT     256
#define DECAYF 0.8f
#define OMDF   0.2f
#define EPSF   1e-5f
#define TH     0.25f

// Output layout (concatenated f32, reference return order)
#define O_Q    0
#define O_IND  8388608
#define O_CS   8421376
#define O_EA   8429568
#define O_EMB  10526720
#define O_TOT  12623872

// smem (float2 units)
#define SA     260            // float2 stride per x row-pair
#define XS_F2  (64 * SA)      // 16640 float2 = 133120 B
#define MG_F2  1536           // merge buffer: 128 rows x 4 wn x 3
#define SM_BYTES ((XS_F2 + MG_F2) * 8)   // 145408

// Scratch
__device__ float g_enorm[K];
__device__ int   g_ind[N_ROWS];
__device__ float g_counts[K];
__device__ float g_esum[K * D];
__device__ float g_S;
__device__ int   g_nflag;
__device__ int   g_flag[N_ROWS];
__device__ int   g_cand[N_ROWS * 3];

__device__ __forceinline__ void mma_tf32(float* c, const uint32_t* a, const uint32_t* b) {
    asm volatile("mma.sync.aligned.m16n8k8.row.col.f32.tf32.tf32.f32 "
        "{%0,%1,%2,%3}, {%4,%5,%6,%7}, {%8,%9}, {%0,%1,%2,%3};"
        : "+f"(c[0]), "+f"(c[1]), "+f"(c[2]), "+f"(c[3])
        : "r"(a[0]), "r"(a[1]), "r"(a[2]), "r"(a[3]), "r"(b[0]), "r"(b[1]));
}

__device__ __forceinline__ void upd3(float s, int c, float* bs, int* bi) {
    if (s > bs[0])      { bs[2]=bs[1]; bi[2]=bi[1]; bs[1]=bs[0]; bi[1]=bi[0]; bs[0]=s; bi[0]=c; }
    else if (s > bs[1]) { bs[2]=bs[1]; bi[2]=bi[1]; bs[1]=s; bi[1]=c; }
    else if (s > bs[2]) { bs[2]=s; bi[2]=c; }
}

// ---------------- zero scratch ----------------
__global__ void zero_kernel() {
    int i = blockIdx.x * blockDim.x + threadIdx.x;
    if (i < K * D) g_esum[i] = 0.0f;
    if (i < K)     g_counts[i] = 0.0f;
    if (i == 0)  { g_S = 0.0f; g_nflag = 0; }
}

// ---------------- ||e_k||^2 ----------------
__global__ void enorm_kernel(const float* __restrict__ embed) {
    int w = (blockIdx.x * blockDim.x + threadIdx.x) >> 5;
    int lane = threadIdx.x & 31;
    if (w >= K) return;
    const float4* p = reinterpret_cast<const float4*>(embed + (size_t)w * D);
    float s = 0.0f;
#pragma unroll
    for (int h = 0; h < 2; h++) {
        float4 v = p[h * 32 + lane];
        s += v.x * v.x + v.y * v.y + v.z * v.z + v.w * v.w;
    }
#pragma unroll
    for (int off = 16; off >= 1; off >>= 1) s += __shfl_xor_sync(0xffffffffu, s, off);
    if (lane == 0) g_enorm[w] = s;
}

// ---------------- tf32 mma.sync scoring, barrier-free mainloop (B direct from L2) ----------------
__global__ void __launch_bounds__(NT, 1)
argmax_mma_kernel(const float* __restrict__ x, const float* __restrict__ embed) {
    extern __shared__ float2 smem2[];
    float2* Xs = smem2;                    // x tile: row-pair interleaved, read-only after staging
    float2* mg = smem2 + XS_F2;            // final merge buffer

    const int tid = threadIdx.x;
    const int wid = tid >> 5, lane = tid & 31;
    const int lg = lane >> 2, lm = lane & 3;
    const int wm = wid >> 2, wn = wid & 3;         // warp grid 2m x 4n
    const int r0 = blockIdx.x * BM;

    // ---- stage x tile: pairs (row, row+8) as float2 ----
#pragma unroll
    for (int t = 0; t < 16; t++) {
        int task = tid + t * NT;                   // 4096 tasks: 64 rowpairs x 64 col-quads
        int rp = task >> 6, cq = task & 63;
        int row = ((rp >> 3) << 4) + (rp & 7);
        const float4 lo = *reinterpret_cast<const float4*>(x + (size_t)(r0 + row) * D + cq * 4);
        const float4 hi = *reinterpret_cast<const float4*>(x + (size_t)(r0 + row + 8) * D + cq * 4);
        float2* dst = Xs + rp * SA + cq * 4;
        dst[0] = make_float2(lo.x, hi.x);
        dst[1] = make_float2(lo.y, hi.y);
        dst[2] = make_float2(lo.z, hi.z);
        dst[3] = make_float2(lo.w, hi.w);
    }
    __syncthreads();                               // the ONLY barrier before the merge

    // B base pointer for this thread: code = tile*128 + wn*32 + nf*8 + lg, col = ks*8 + lm
    const float* eb = embed + (size_t)(wn * 32 + lg) * D + lm;

    float acc[64];
    float bs[24]; int bi[24];
#pragma unroll
    for (int i = 0; i < 24; i++) { bs[i] = __int_as_float(0xff800000); bi[i] = 0x7fffffff; }
#pragma unroll
    for (int i = 0; i < 64; i++) acc[i] = 0.0f;

    uint32_t bA[8], bB[8];
    // preload g=0 (-> bA) and g=1 (-> bB); g indexes 2048 k8-steps (tile = g>>5, ks = g&31)
#pragma unroll
    for (int nf = 0; nf < 4; nf++) {
        const float* p0 = eb + nf * 2048;                  // tile 0, ks 0
        bA[nf * 2 + 0] = __float_as_uint(p0[0]);
        bA[nf * 2 + 1] = __float_as_uint(p0[4]);
        const float* p1 = eb + nf * 2048 + 8;              // tile 0, ks 1
        bB[nf * 2 + 0] = __float_as_uint(p1[0]);
        bB[nf * 2 + 1] = __float_as_uint(p1[4]);
    }

    for (int g = 0; g < 2048; g += 2) {
        // ---- even step g (uses bA) ----
        {
            const int c0 = (g & 31) * 8;
            uint32_t a[4][4];
#pragma unroll
            for (int mf = 0; mf < 4; mf++) {
                int rp = (wm * 4 + mf) * 8 + lg;
                float2 v0 = Xs[rp * SA + c0 + lm];
                float2 v1 = Xs[rp * SA + c0 + lm + 4];
                a[mf][0] = __float_as_uint(v0.x); a[mf][1] = __float_as_uint(v0.y);
                a[mf][2] = __float_as_uint(v1.x); a[mf][3] = __float_as_uint(v1.y);
            }
#pragma unroll
            for (int mf = 0; mf < 4; mf++)
#pragma unroll
                for (int nf = 0; nf < 4; nf++)
                    mma_tf32(acc + (mf * 4 + nf) * 4, a[mf], bA + nf * 2);
            // prefetch g+2 into bA (distance 2)
            if (g + 2 < 2048) {
                int g2 = g + 2;
                const float* pb = eb + (size_t)(g2 >> 5) * 32768 + (g2 & 31) * 8;
#pragma unroll
                for (int nf = 0; nf < 4; nf++) {
                    bA[nf * 2 + 0] = __float_as_uint(pb[nf * 2048]);
                    bA[nf * 2 + 1] = __float_as_uint(pb[nf * 2048 + 4]);
                }
            }
        }
        // ---- odd step g+1 (uses bB) ----
        {
            const int c0 = ((g + 1) & 31) * 8;
            uint32_t a[4][4];
#pragma unroll
            for (int mf = 0; mf < 4; mf++) {
                int rp = (wm * 4 + mf) * 8 + lg;
                float2 v0 = Xs[rp * SA + c0 + lm];
                float2 v1 = Xs[rp * SA + c0 + lm + 4];
                a[mf][0] = __float_as_uint(v0.x); a[mf][1] = __float_as_uint(v0.y);
                a[mf][2] = __float_as_uint(v1.x); a[mf][3] = __float_as_uint(v1.y);
            }
#pragma unroll
            for (int mf = 0; mf < 4; mf++)
#pragma unroll
                for (int nf = 0; nf < 4; nf++)
                    mma_tf32(acc + (mf * 4 + nf) * 4, a[mf], bB + nf * 2);
            if (g + 3 < 2048) {
                int g3 = g + 3;
                const float* pb = eb + (size_t)(g3 >> 5) * 32768 + (g3 & 31) * 8;
#pragma unroll
                for (int nf = 0; nf < 4; nf++) {
                    bB[nf * 2 + 0] = __float_as_uint(pb[nf * 2048]);
                    bB[nf * 2 + 1] = __float_as_uint(pb[nf * 2048 + 4]);
                }
            }
        }
        // ---- epilogue at end of code tile (g+1 has ks==31) ----
        if (((g + 1) & 31) == 31) {
            int nt = (g + 1) >> 5;
            int ntb = nt * 128 + wn * 32;
#pragma unroll
            for (int nf = 0; nf < 4; nf++) {
                int cb = ntb + nf * 8 + 2 * lm;
                float e0 = __ldg(g_enorm + cb), e1 = __ldg(g_enorm + cb + 1);
#pragma unroll
                for (int mf = 0; mf < 4; mf++) {
                    float* ac = acc + (mf * 4 + nf) * 4;
                    upd3(fmaf(2.0f, ac[0], -e0), cb,     bs + (mf * 2) * 3,     bi + (mf * 2) * 3);
                    upd3(fmaf(2.0f, ac[1], -e1), cb + 1, bs + (mf * 2) * 3,     bi + (mf * 2) * 3);
                    upd3(fmaf(2.0f, ac[2], -e0), cb,     bs + (mf * 2 + 1) * 3, bi + (mf * 2 + 1) * 3);
                    upd3(fmaf(2.0f, ac[3], -e1), cb + 1, bs + (mf * 2 + 1) * 3, bi + (mf * 2 + 1) * 3);
                }
            }
#pragma unroll
            for (int i = 0; i < 64; i++) acc[i] = 0.0f;
        }
    }

    // ---- merge top-3: (1) across the 4 lm lanes sharing each row, (2) across the 4 wn warps ----
#pragma unroll
    for (int rid = 0; rid < 8; rid++) {
        float* s = bs + rid * 3; int* ii = bi + rid * 3;
#pragma unroll
        for (int off = 1; off <= 2; off <<= 1) {
            float r0s = __shfl_xor_sync(0xffffffffu, s[0], off);
            float r1s = __shfl_xor_sync(0xffffffffu, s[1], off);
            float r2s = __shfl_xor_sync(0xffffffffu, s[2], off);
            int r0i = __shfl_xor_sync(0xffffffffu, ii[0], off);
            int r1i = __shfl_xor_sync(0xffffffffu, ii[1], off);
            int r2i = __shfl_xor_sync(0xffffffffu, ii[2], off);
            upd3(r0s, r0i, s, ii);
            upd3(r1s, r1i, s, ii);
            upd3(r2s, r2i, s, ii);
        }
        if (lm == 0) {
            int mf = rid >> 1, half = rid & 1;
            int rloc = wm * 64 + mf * 16 + half * 8 + lg;   // 0..127
#pragma unroll
            for (int q = 0; q < 3; q++)
                mg[(rloc * 4 + wn) * 3 + q] = make_float2(s[q], __int_as_float(ii[q]));
        }
    }
    __syncthreads();
    if (tid < BM) {
        float fs[3]; int fi[3];
#pragma unroll
        for (int q = 0; q < 3; q++) { fs[q] = __int_as_float(0xff800000); fi[q] = 0x7fffffff; }
#pragma unroll
        for (int w = 0; w < 4; w++)
#pragma unroll
            for (int q = 0; q < 3; q++) {
                float2 v = mg[(tid * 4 + w) * 3 + q];
                upd3(v.x, __float_as_int(v.y), fs, fi);
            }
        int row = r0 + tid;
        g_ind[row] = fi[0];
        if (fs[0] - fs[1] < TH) {
            int nc = (fs[0] - fs[2] < TH) ? 3 : 2;
            g_cand[row * 3 + 0] = fi[0];
            g_cand[row * 3 + 1] = fi[1];
            g_cand[row * 3 + 2] = fi[2];
            int p = atomicAdd(&g_nflag, 1);
            g_flag[p] = row | (nc << 20);
        }
    }
}

// ---------------- exact fp32 rescore of flagged rows' candidates ----------------
__global__ void cleanup_kernel(const float* __restrict__ x, const float* __restrict__ embed) {
    int gw = (blockIdx.x * blockDim.x + threadIdx.x) >> 5;
    int lane = threadIdx.x & 31;
    int nw = (gridDim.x * blockDim.x) >> 5;
    int nf = g_nflag;
    for (int j = gw; j < nf; j += nw) {
        int e = g_flag[j];
        int row = e & 0xFFFFF, nc = e >> 20;
        const float4* xp = reinterpret_cast<const float4*>(x + (size_t)row * D);
        float4 xa = xp[lane], xb = xp[32 + lane];
        float best = __int_as_float(0xff800000);
        int bidx2 = 0x7fffffff;
        for (int q = 0; q < nc; q++) {
            int cand = g_cand[row * 3 + q];
            const float4* ep = reinterpret_cast<const float4*>(embed + (size_t)cand * D);
            float4 ea = ep[lane], ebv = ep[32 + lane];
            float s = xa.x * ea.x + xa.y * ea.y + xa.z * ea.z + xa.w * ea.w
                    + xb.x * ebv.x + xb.y * ebv.y + xb.z * ebv.z + xb.w * ebv.w;
#pragma unroll
            for (int off = 16; off >= 1; off >>= 1) s += __shfl_xor_sync(0xffffffffu, s, off);
            s = 2.0f * s - g_enorm[cand];
            if (s > best || (s == best && cand < bidx2)) { best = s; bidx2 = cand; }
        }
        if (lane == 0) g_ind[row] = bidx2;
    }
}

// ---------------- gather quantize + scatter counts/embed_sum + indices ----------------
__global__ void scatter_kernel(const float* __restrict__ x, const float* __restrict__ embed,
                               float* __restrict__ out, int out_size) {
    int w = (blockIdx.x * blockDim.x + threadIdx.x) >> 5;
    int lane = threadIdx.x & 31;
    if (w >= N_ROWS) return;
    int idx = g_ind[w];
    const float4* esrc = reinterpret_cast<const float4*>(embed + (size_t)idx * D);
    const float4* xsrc = reinterpret_cast<const float4*>(x + (size_t)w * D);
    float4* qdst = reinterpret_cast<float4*>(out + (size_t)w * D);
    bool wq = (out_size >= O_IND);
#pragma unroll
    for (int h = 0; h < 2; h++) {
        int j = h * 32 + lane;
        if (wq) qdst[j] = esrc[j];
        float4 xv = xsrc[j];
        float* dst = g_esum + (size_t)idx * D + j * 4;
        atomicAdd(dst + 0, xv.x);
        atomicAdd(dst + 1, xv.y);
        atomicAdd(dst + 2, xv.z);
        atomicAdd(dst + 3, xv.w);
    }
    if (lane == 0) {
        atomicAdd(&g_counts[idx], 1.0f);
        if (out_size >= O_CS) out[O_IND + w] = (float)idx;
    }
}

// ---------------- new_cluster_size + sum reduction ----------------
__global__ void cs_kernel(const float* __restrict__ cs, float* __restrict__ out, int out_size) {
    __shared__ float red[8];
    int k = blockIdx.x * blockDim.x + threadIdx.x;
    float v = 0.0f;
    if (k < K) {
        v = cs[k] * DECAYF + g_counts[k] * OMDF;
        if (out_size >= O_EA) out[O_CS + k] = v;
    }
#pragma unroll
    for (int off = 16; off >= 1; off >>= 1) v += __shfl_xor_sync(0xffffffffu, v, off);
    int lane = threadIdx.x & 31, wid = threadIdx.x >> 5;
    if (lane == 0) red[wid] = v;
    __syncthreads();
    if (wid == 0) {
        float s = (lane < (blockDim.x >> 5)) ? red[lane] : 0.0f;
#pragma unroll
        for (int off = 4; off >= 1; off >>= 1) s += __shfl_xor_sync(0xffffffffu, s, off);
        if (lane == 0) atomicAdd(&g_S, s);
    }
}

// ---------------- new_embed_avg + new_embed ----------------
__global__ void finalize_kernel(const float* __restrict__ cs, const float* __restrict__ ea,
                                float* __restrict__ out, int out_size) {
    int i = blockIdx.x * blockDim.x + threadIdx.x;
    if (i >= K * D) return;
    int k = i >> 8;
    float nea = ea[i] * DECAYF + g_esum[i] * OMDF;
    float ncs = cs[k] * DECAYF + g_counts[k] * OMDF;
    float S = g_S;
    float smoothed = (ncs + EPSF) / (S + (float)K * EPSF) * S;
    if (out_size >= O_EMB) out[O_EA + i] = nea;
    if (out_size >= O_TOT) out[O_EMB + i] = nea / smoothed;
}

extern "C" void kernel_launch(void* const* d_in, const int* in_sizes, int n_in,
                              void* d_out, int out_size) {
    const float* x     = (const float*)d_in[0];
    const float* embed = (const float*)d_in[1];
    const float* cs    = (const float*)d_in[2];
    const float* ea    = (const float*)d_in[3];
    float* out = (float*)d_out;

    cudaFuncSetAttribute(argmax_mma_kernel, cudaFuncAttributeMaxDynamicSharedMemorySize, SM_BYTES);

    zero_kernel<<<(K * D + 1023) / 1024, 1024>>>();
    enorm_kernel<<<K / 8, 256>>>(embed);
    argmax_mma_kernel<<<N_ROWS / BM, NT, SM_BYTES>>>(x, embed);
    cleanup_kernel<<<128, 256>>>(x, embed);
    scatter_kernel<<<N_ROWS / 8, 256>>>(x, embed, out, out_size);
    cs_kernel<<<(K + 255) / 256, 256>>>(cs, out, out_size);
    finalize_kernel<<<(K * D + 255) / 256, 256>>>(cs, ea, out, out_size);
}